// round 2
// baseline (speedup 1.0000x reference)
#include <cuda_runtime.h>
#include <cstdint>

// 2x nearest-neighbor upsample:
//   in : (16, 64, 256, 256) fp32  -> treated as (BC=1024, H=256, W=256)
//   out: (16, 64, 512, 512) fp32
// out[bc, H, W] = in[bc, H/2, W/2]
//
// One thread per input float4 (4 adjacent w elems). Emits two float4s
// ({x,x,y,y} and {z,z,w,w}) on each of output rows 2h and 2h+1.
// All accesses fully coalesced: LDG.128 in, 4x STG.128 out.

static constexpr int  H_IN   = 256;
static constexpr int  W_IN   = 256;
static constexpr int  BC     = 16 * 64;            // 1024
static constexpr int  W4_IN  = W_IN / 4;           // 64 float4 per input row
static constexpr int  W4_OUT = (W_IN * 2) / 4;     // 128 float4 per output row
static constexpr long N_F4   = (long)BC * H_IN * W4_IN;  // 16,777,216 threads

__global__ __launch_bounds__(256)
void upsample2x_kernel(const float4* __restrict__ in, float4* __restrict__ out) {
    long i = (long)blockIdx.x * blockDim.x + threadIdx.x;
    if (i >= N_F4) return;

    float4 v = __ldg(&in[i]);
    float4 lo = make_float4(v.x, v.x, v.y, v.y);
    float4 hi = make_float4(v.z, v.z, v.w, v.w);

    // decompose i -> (bc, h, w4); all power-of-two
    long w4 = i & (W4_IN - 1);        // i % 64
    long h  = (i >> 6) & (H_IN - 1);  // (i / 64) % 256
    long bc = i >> 14;                // i / (64*256)

    // output as float4 array: row stride = 128 float4, image stride = 512*128
    long base = bc * (long)(2 * H_IN * W4_OUT) + (2 * h) * W4_OUT + 2 * w4;
    out[base]              = lo;   // row 2h, cols [8w4, 8w4+4)
    out[base + 1]          = hi;   // row 2h, cols [8w4+4, 8w4+8)
    out[base + W4_OUT]     = lo;   // row 2h+1
    out[base + W4_OUT + 1] = hi;
}

extern "C" void kernel_launch(void* const* d_in, const int* in_sizes, int n_in,
                              void* d_out, int out_size) {
    (void)in_sizes; (void)n_in; (void)out_size;
    const float4* in  = (const float4*)d_in[0];
    float4*       out = (float4*)d_out;

    const int threads = 256;
    const long blocks = (N_F4 + threads - 1) / threads;  // 65536
    upsample2x_kernel<<<(unsigned)blocks, threads>>>(in, out);
}

// round 3
// speedup vs baseline: 1.1568x; 1.1568x over previous
#include <cuda_runtime.h>
#include <cstdint>

// 2x nearest-neighbor upsample:
//   in : (16, 64, 256, 256) fp32  -> (BC=1024, H=256, W=256)
//   out: (16, 64, 512, 512) fp32
// out[bc, H, W] = in[bc, H/2, W/2]
//
// One thread per input float8 (8 adjacent w elems), using sm_100+ 256-bit
// vector ld/st (LDG.E.256 / STG.E.256). Each thread: 1x v8 load, 4x v8 store
// (two 32B chunks on each of output rows 2h and 2h+1). Fully coalesced.

static constexpr int  H_IN   = 256;
static constexpr int  W_IN   = 256;
static constexpr int  BC     = 16 * 64;              // 1024
static constexpr int  W8_IN  = W_IN / 8;             // 32 float8 per input row
static constexpr int  W_OUT  = W_IN * 2;             // 512 floats per output row
static constexpr long N_F8   = (long)BC * H_IN * W8_IN;  // 8,388,608 threads

__device__ __forceinline__ void ldg256(const float* p, float& a0, float& a1, float& a2, float& a3,
                                       float& a4, float& a5, float& a6, float& a7) {
    asm volatile("ld.global.nc.v8.f32 {%0,%1,%2,%3,%4,%5,%6,%7}, [%8];"
                 : "=f"(a0), "=f"(a1), "=f"(a2), "=f"(a3),
                   "=f"(a4), "=f"(a5), "=f"(a6), "=f"(a7)
                 : "l"(p));
}

__device__ __forceinline__ void stg256(float* p, float a0, float a1, float a2, float a3,
                                       float a4, float a5, float a6, float a7) {
    asm volatile("st.global.v8.f32 [%0], {%1,%2,%3,%4,%5,%6,%7,%8};"
                 :: "l"(p),
                    "f"(a0), "f"(a1), "f"(a2), "f"(a3),
                    "f"(a4), "f"(a5), "f"(a6), "f"(a7)
                 : "memory");
}

__global__ __launch_bounds__(256)
void upsample2x_kernel(const float* __restrict__ in, float* __restrict__ out) {
    long i = (long)blockIdx.x * blockDim.x + threadIdx.x;
    if (i >= N_F8) return;

    float v0, v1, v2, v3, v4, v5, v6, v7;
    ldg256(in + i * 8, v0, v1, v2, v3, v4, v5, v6, v7);

    // decompose i -> (bc, h, w8); all power-of-two
    long w8 = i & (W8_IN - 1);        // i % 32
    long h  = (i >> 5) & (H_IN - 1);  // (i / 32) % 256
    long bc = i >> 13;                // i / (32*256)

    // output float offset: image stride 512*512, row stride 512
    float* r0 = out + bc * (long)(2 * H_IN * W_OUT) + (2 * h) * W_OUT + 16 * w8;
    float* r1 = r0 + W_OUT;

    // width-duplicated halves
    stg256(r0,     v0, v0, v1, v1, v2, v2, v3, v3);
    stg256(r0 + 8, v4, v4, v5, v5, v6, v6, v7, v7);
    stg256(r1,     v0, v0, v1, v1, v2, v2, v3, v3);
    stg256(r1 + 8, v4, v4, v5, v5, v6, v6, v7, v7);
}

extern "C" void kernel_launch(void* const* d_in, const int* in_sizes, int n_in,
                              void* d_out, int out_size) {
    (void)in_sizes; (void)n_in; (void)out_size;
    const float* in  = (const float*)d_in[0];
    float*       out = (float*)d_out;

    const int threads = 256;
    const long blocks = (N_F8 + threads - 1) / threads;  // 32768
    upsample2x_kernel<<<(unsigned)blocks, threads>>>(in, out);
}

// round 4
// speedup vs baseline: 1.2705x; 1.0983x over previous
#include <cuda_runtime.h>
#include <cstdint>

// 2x nearest-neighbor upsample via SMEM staging + TMA bulk stores.
//   in : (16, 64, 256, 256) fp32  -> (BC=1024, H=256, W=256)
//   out: (16, 64, 512, 512) fp32
//
// Per CTA (256 threads): 8 input rows.
//   - each lane loads a float2 (coalesced LDG.64), writes width-duplicated
//     float4 to SMEM (conflict-free STS.128) -> 8 upsampled rows (16 KB).
//   - height duplication done by TMA: 2 bulk stores per staged row
//     (output rows 2h and 2h+1), bypassing L1/LSU on the store path.

static constexpr int H_IN  = 256;
static constexpr int W_IN  = 256;
static constexpr int BC    = 16 * 64;   // 1024
static constexpr int ROWS  = 8;         // input rows per CTA
static constexpr int W_OUT = 512;
static constexpr int BLOCKS_PER_IMG = H_IN / ROWS;          // 32
static constexpr int GRID = BC * BLOCKS_PER_IMG;            // 32768
static constexpr int ROW_BYTES = W_OUT * 4;                 // 2048

__global__ __launch_bounds__(256)
void upsample2x_tma_kernel(const float* __restrict__ in, float* __restrict__ out) {
    __shared__ alignas(128) float s[ROWS * W_OUT];   // 16 KB staged upsampled rows

    const int t   = blockIdx.x;
    const int bc  = t >> 5;            // t / 32
    const int r0  = (t & 31) * ROWS;   // first input row of this tile
    const int tid = threadIdx.x;

    const float2* inp = (const float2*)(in + (long)bc * H_IN * W_IN + (long)r0 * W_IN);

    // 8 rows * 128 float2 = 1024 items; 4 per thread.
    #pragma unroll
    for (int it = 0; it < 4; ++it) {
        int k   = tid + it * 256;
        int row = k >> 7;       // 0..7
        int c2  = k & 127;      // float2 column
        float2 v = __ldg(&inp[row * 128 + c2]);
        float4 o = make_float4(v.x, v.x, v.y, v.y);
        *(float4*)&s[row * W_OUT + 4 * c2] = o;   // lane-consecutive 16B: conflict-free
    }

    // Order generic-proxy SMEM writes before async-proxy TMA reads.
    asm volatile("fence.proxy.async.shared::cta;" ::: "memory");
    __syncthreads();

    if (tid == 0) {
        uint32_t sbase = (uint32_t)__cvta_generic_to_shared(s);
        float* obase = out + (long)bc * (2 * H_IN) * W_OUT + (long)(2 * r0) * W_OUT;
        #pragma unroll
        for (int r = 0; r < ROWS; ++r) {
            uint32_t src = sbase + r * ROW_BYTES;
            float* d0 = obase + (long)(2 * r) * W_OUT;
            asm volatile("cp.async.bulk.global.shared::cta.bulk_group [%0], [%1], %2;"
                         :: "l"(d0), "r"(src), "r"(ROW_BYTES) : "memory");
            asm volatile("cp.async.bulk.global.shared::cta.bulk_group [%0], [%1], %2;"
                         :: "l"(d0 + W_OUT), "r"(src), "r"(ROW_BYTES) : "memory");
        }
        asm volatile("cp.async.bulk.commit_group;" ::: "memory");
        asm volatile("cp.async.bulk.wait_group 0;" ::: "memory");
    }
    // No thread may exit while TMA still reads this CTA's SMEM.
    __syncthreads();
}

extern "C" void kernel_launch(void* const* d_in, const int* in_sizes, int n_in,
                              void* d_out, int out_size) {
    (void)in_sizes; (void)n_in; (void)out_size;
    const float* in  = (const float*)d_in[0];
    float*       out = (float*)d_out;
    upsample2x_tma_kernel<<<GRID, 256>>>(in, out);
}